// round 13
// baseline (speedup 1.0000x reference)
#include <cuda_runtime.h>
#include <cuda_bf16.h>

#define N_PRED 2048
#define T_RUNS 16
#define M_BOX  2048
#define EPS_F  1e-7f

#define GBY     16
#define GBX     32
#define NBINS   (GBY*GBX)       // 512
#define BIN_ORG (-28.0f)
#define INV_Y   (1.0f/42.0f)    // 16*42 = 672 covers [-28, 644)
#define INV_X   (1.0f/21.0f)    // 32*21 = 672
#define WH_MAX  55.0f           // box w,h in [5,55)
#define CAP     1280            // smem slab capacity (5 rows avg ~640)
#define SBW     (GBX + 1)       // 33 prefix entries per row

// ---- device scratch (no allocations allowed) ----
__device__ float4 g_sbox[T_RUNS][M_BOX];      // binned boxes (x1,y1,x2,y2)
__device__ int    g_bstart[T_RUNS][NBINS+1];  // box bin prefix offsets per run
__device__ float4 g_pbox[N_PRED];             // pred boxes, bin-sorted
__device__ int    g_perm[N_PRED];             // sorted slot -> original pred idx
__device__ int    g_pstart[NBINS+1];          // pred bin prefix offsets

__device__ __forceinline__ int biny(float v) {
    int b = (int)floorf((v - BIN_ORG) * INV_Y);
    return min(max(b, 0), GBY - 1);
}
__device__ __forceinline__ int binx(float v) {
    int b = (int)floorf((v - BIN_ORG) * INV_X);
    return min(max(b, 0), GBX - 1);
}

// ---------------------------------------------------------------------------
// prep: unchanged from R10/R11 (512 y16 x x32 bins) — passed twice.
// ---------------------------------------------------------------------------
__global__ __launch_bounds__(256)
void prep_kernel(const float* __restrict__ pred,
                 const float* __restrict__ dropout_preds,
                 float* __restrict__ out)
{
    __shared__ int cnt[NBINS];
    __shared__ int wsum[8];
    const int tid  = threadIdx.x;
    const int lane = tid & 31, wid = tid >> 5;
    const bool is_box_block = (blockIdx.x < T_RUNS);

    cnt[tid] = 0;
    cnt[tid + 256] = 0;
    __syncthreads();

    float4 box[8];
    int    bin[8];
    if (is_box_block) {
        const float* src = dropout_preds + (size_t)blockIdx.x * M_BOX * 6;
        #pragma unroll
        for (int k = 0; k < M_BOX / 256; ++k) {
            const float* b6 = src + (tid + k * 256) * 6;
            box[k] = make_float4(b6[0], b6[1], b6[2], b6[3]);
            bin[k] = biny(box[k].y) * GBX + binx(box[k].x);
            atomicAdd(&cnt[bin[k]], 1);
        }
    } else {
        #pragma unroll
        for (int k = 0; k < N_PRED / 256; ++k) {
            int p = tid + k * 256;
            const float* a = pred + p * 6;
            box[k] = make_float4(a[0], a[1], a[2], a[3]);
            bin[k] = biny(box[k].y) * GBX + binx(box[k].x);
            atomicAdd(&cnt[bin[k]], 1);
            out[p] = 0.0f;        // out is poisoned; zero before match
        }
    }
    __syncthreads();

    const int v0 = cnt[2 * tid], v1 = cnt[2 * tid + 1];
    const int tv = v0 + v1;
    int inc = tv;
    #pragma unroll
    for (int o = 1; o < 32; o <<= 1) {
        int n = __shfl_up_sync(0xffffffffu, inc, o);
        if (lane >= o) inc += n;
    }
    if (lane == 31) wsum[wid] = inc;
    __syncthreads();
    if (wid == 0) {
        int w = (lane < 8) ? wsum[lane] : 0;
        int wi = w;
        #pragma unroll
        for (int o = 1; o < 8; o <<= 1) {
            int n = __shfl_up_sync(0xffffffffu, wi, o);
            if (lane >= o) wi += n;
        }
        if (lane < 8) wsum[lane] = wi - w;
    }
    __syncthreads();
    const int excl   = inc - tv + wsum[wid];
    const int start0 = excl;
    const int start1 = excl + v0;
    cnt[2 * tid]     = start0;
    cnt[2 * tid + 1] = start1;
    __syncthreads();

    if (is_box_block) {
        const int t = blockIdx.x;
        g_bstart[t][2 * tid]     = start0;
        g_bstart[t][2 * tid + 1] = start1;
        if (tid == 0) g_bstart[t][NBINS] = M_BOX;
        #pragma unroll
        for (int k = 0; k < M_BOX / 256; ++k) {
            int pos = atomicAdd(&cnt[bin[k]], 1);
            g_sbox[t][pos] = box[k];
        }
    } else {
        g_pstart[2 * tid]     = start0;
        g_pstart[2 * tid + 1] = start1;
        if (tid == 0) g_pstart[NBINS] = N_PRED;
        #pragma unroll
        for (int k = 0; k < N_PRED / 256; ++k) {
            int pos = atomicAdd(&cnt[bin[k]], 1);
            g_pbox[pos] = box[k];
            g_perm[pos] = tid + k * 256;
        }
    }
}

// ---------------------------------------------------------------------------
// match: CTA = (half, yr, t), 128 threads, ONE THREAD PER PRED (the only
// ~12.1us architecture). Simple full 5-row slab fill (R4) + 32 x-bins (R10's
// win) + smem-staged preds (kills the L2 LDG at every scan head) + unroll 8.
// Per-pair fp sequence identical; per-thread per-row early exit preserved.
// ---------------------------------------------------------------------------
__global__ __launch_bounds__(128)
void match_kernel(float* __restrict__ out)
{
    __shared__ float4 sbox[CAP];
    __shared__ float  snarea[CAP];
    __shared__ int    sbs[5 * SBW];
    __shared__ float4 spred[128];
    __shared__ int    sperm[128];

    const int tid  = threadIdx.x;
    const int half = blockIdx.x;
    const int yr   = blockIdx.y;
    const int t    = blockIdx.z;

    const int r0 = max(yr - 2, 0), r1 = min(yr + 2, GBY - 1);
    const int nr = r1 - r0 + 1;

    const int base = __ldg(&g_bstart[t][r0 * GBX]);
    const int n    = __ldg(&g_bstart[t][(r1 + 1) * GBX]) - base;

    // prefix entries for the 5 rows
    for (int i = tid; i < nr * SBW; i += 128) {
        const int r = i / SBW, b = i - r * SBW;
        sbs[i] = g_bstart[t][(r0 + r) * GBX + b];
    }

    // stage this CTA's preds (coalesced, overlaps the slab fill)
    const int ps  = g_pstart[yr * GBX], pe = g_pstart[(yr + 1) * GBX];
    const int mid = (ps + pe) >> 1;
    const int seg_s = half ? mid : ps;
    const int seg_e = half ? pe  : mid;
    const int seg_n = seg_e - seg_s;
    if (tid < seg_n && tid < 128) {
        spred[tid] = g_pbox[seg_s + tid];
        sperm[tid] = g_perm[seg_s + tid];
    }

    // slab fill
    const int ncap = min(n, CAP);
    for (int i = tid; i < ncap; i += 128) {
        float4 b  = g_sbox[t][base + i];
        sbox[i]   = b;
        snarea[i] = -((b.z - b.x) * (b.w - b.y));
    }
    __syncthreads();

    const bool all_smem = (n <= CAP);        // always true for uniform data

    for (int si = tid; si < seg_n; si += 128) {
        const float4 a = (si < 128) ? spred[si] : g_pbox[seg_s + si];
        const int    p = (si < 128) ? sperm[si] : g_perm[seg_s + si];
        const float thr = (a.z - a.x) * (a.w - a.y) + EPS_F;

        const int xb0 = binx(a.x - WH_MAX), xb1 = binx(a.z);
        const int yb0 = max(biny(a.y - WH_MAX), r0);
        const int yb1 = min(biny(a.w), r1);

        float best = -1e30f;
        if (all_smem) {
            for (int yb = yb0; yb <= yb1; ++yb) {
                const int rb = (yb - r0) * SBW;
                const int s  = sbs[rb + xb0] - base;
                const int e  = sbs[rb + xb1 + 1] - base;
                #pragma unroll 8
                for (int m = s; m < e; ++m) {
                    float4 b  = sbox[m];
                    float ix1 = fmaxf(a.x, b.x);
                    float iy1 = fmaxf(a.y, b.y);
                    float ix2 = fminf(a.z, b.z);
                    float iy2 = fminf(a.w, b.w);
                    float dx  = fmaxf(ix2 - ix1, 0.0f);
                    float dy  = iy2 - iy1;          // dy<0 => inter<=0 < thr
                    best = fmaxf(best, fmaf(3.0f, dx * dy, snarea[m]));
                }
                if (best > thr) break;
            }
        } else {                                    // safety fallback (gmem)
            for (int yb = yb0; yb <= yb1; ++yb) {
                const int rb = (yb - r0) * SBW;
                const int s  = sbs[rb + xb0];
                const int e  = sbs[rb + xb1 + 1];
                for (int m = s; m < e; ++m) {
                    float4 b  = g_sbox[t][m];
                    float na  = -((b.z - b.x) * (b.w - b.y));
                    float ix1 = fmaxf(a.x, b.x);
                    float iy1 = fmaxf(a.y, b.y);
                    float ix2 = fminf(a.z, b.z);
                    float iy2 = fminf(a.w, b.w);
                    float dx  = fmaxf(ix2 - ix1, 0.0f);
                    float dy  = iy2 - iy1;
                    best = fmaxf(best, fmaf(3.0f, dx * dy, na));
                }
                if (best > thr) break;
            }
        }

        // 16 adds of exactly 1/16: order-independent & exact -> deterministic
        if (best > thr) atomicAdd(&out[p], 1.0f / (float)T_RUNS);
    }
}

extern "C" void kernel_launch(void* const* d_in, const int* in_sizes, int n_in,
                              void* d_out, int out_size)
{
    const float* pred          = (const float*)d_in[0]; // [2048, 6]
    const float* dropout_preds = (const float*)d_in[1]; // [16, 2048, 6]
    // d_in[2] (dropout_cls_confs) unused by the reference computation.
    float* out = (float*)d_out;                          // [2048]

    prep_kernel<<<T_RUNS + 1, 256>>>(pred, dropout_preds, out);
    match_kernel<<<dim3(2, GBY, T_RUNS), 128>>>(out);
}